// round 4
// baseline (speedup 1.0000x reference)
#include <cuda_runtime.h>
#include <mma.h>
#include <cstdint>

using namespace nvcuda;

#define D_MODEL 1024
#define N_HEADS 16
#define DK      64
#define BATCH   2
#define SEQ     2048
#define MTOT    (BATCH*SEQ)
#define QKVLD   (3*D_MODEL)   // 3072

// ------------------------- scratch (no allocs allowed) ----------------------
__device__ float g_xt [(size_t)MTOT * D_MODEL];           // tf32-rounded x
__device__ float g_wt [(size_t)4 * D_MODEL * D_MODEL];    // tf32-rounded Wq,Wk,Wv,Wo
__device__ float g_QKV[(size_t)MTOT * QKVLD];             // fused Q|K|V, ld=3072
__device__ float g_Vt [(size_t)MTOT * D_MODEL];           // [b,h][dk][seq]
__device__ float g_O  [(size_t)MTOT * D_MODEL];

// ------------------------- helpers ------------------------------------------
__device__ __forceinline__ float tf32r(float x) {
    uint32_t u;
    asm("cvt.rna.tf32.f32 %0, %1;" : "=r"(u) : "f"(x));
    return __uint_as_float(u);
}
__device__ __forceinline__ uint32_t smem_u32(const void* p) {
    uint32_t a;
    asm("{ .reg .u64 t; cvta.to.shared.u64 t, %1; cvt.u32.u64 %0, t; }" : "=r"(a) : "l"(p));
    return a;
}
__device__ __forceinline__ void cp16(uint32_t dst, const void* src) {
    asm volatile("cp.async.cg.shared.global [%0], [%1], 16;" :: "r"(dst), "l"(src));
}
__device__ __forceinline__ void cp_commit() {
    asm volatile("cp.async.commit_group;" ::: "memory");
}
template<int N> __device__ __forceinline__ void cp_wait() {
    asm volatile("cp.async.wait_group %0;" :: "n"(N) : "memory");
}

// ------------------------- tf32 WMMA GEMM -----------------------------------
// C[m,n] = scale * sum_k A[m,k] * B[n,k]  (A,B K-major), TILE_M=128, BK=32.
// 256 threads = 8 warps in 2(M) x 4(N); warp tile = 64 x (TILE_N/4).
#define NSTAGE 3
#define BK     32
#define LDS    40

template<int TILE_N, bool ROUND>
__global__ void __launch_bounds__(256)
wmma_gemm(const float* __restrict__ A, const float* __restrict__ B, float* __restrict__ C,
          int K, int lda, int ldb, int ldc, float scale,
          long long sAhi, long long sAlo, long long sBhi, long long sBlo,
          long long sChi, long long sClo)
{
    constexpr int AELEM = 128 * LDS;
    constexpr int BELEM = TILE_N * LDS;
    constexpr int NB    = TILE_N / 64;

    extern __shared__ float sm[];
    float* sA = sm;
    float* sB = sm + (size_t)NSTAGE * AELEM;

    const int tid = threadIdx.x;
    const int wid = tid >> 5;
    const int warp_m = wid & 1;
    const int warp_n = wid >> 1;

    const int z  = blockIdx.z;
    const int zh = z >> 4, zl = z & 15;
    const float* Ao = A + (size_t)zh * sAhi + (size_t)zl * sAlo;
    const float* Bo = B + (size_t)zh * sBhi + (size_t)zl * sBlo;
    float*       Co = C + (size_t)zh * sChi + (size_t)zl * sClo;

    const int m0 = blockIdx.y * 128;
    const int n0 = blockIdx.x * TILE_N;
    const int nch = K >> 5;

    wmma::fragment<wmma::accumulator, 16, 16, 8, float> cf[4][NB];
    #pragma unroll
    for (int i = 0; i < 4; i++)
        #pragma unroll
        for (int j = 0; j < NB; j++)
            wmma::fill_fragment(cf[i][j], 0.0f);

    auto load = [&](int s, int c) {
        const int k0 = c * BK;
        uint32_t aB = smem_u32(sA + (size_t)s * AELEM);
        uint32_t bB = smem_u32(sB + (size_t)s * BELEM);
        #pragma unroll
        for (int j = 0; j < 4; j++) {
            int f = tid + j * 256, r = f >> 3, q = f & 7;
            cp16(aB + (uint32_t)(r * LDS + q * 4) * 4,
                 Ao + (size_t)(m0 + r) * lda + k0 + q * 4);
        }
        #pragma unroll
        for (int j = 0; j < TILE_N / 32; j++) {
            int f = tid + j * 256, r = f >> 3, q = f & 7;
            cp16(bB + (uint32_t)(r * LDS + q * 4) * 4,
                 Bo + (size_t)(n0 + r) * ldb + k0 + q * 4);
        }
        cp_commit();
    };

    const int P0 = (nch < NSTAGE - 1) ? nch : NSTAGE - 1;
    for (int c = 0; c < P0; c++) load(c, c);

    for (int c = 0; c < nch; c++) {
        const int s = c % NSTAGE;
        if (c + NSTAGE - 1 < nch) cp_wait<NSTAGE - 2>(); else cp_wait<0>();
        __syncthreads();
        if (c + NSTAGE - 1 < nch) load((c + NSTAGE - 1) % NSTAGE, c + NSTAGE - 1);

        const float* As = sA + (size_t)s * AELEM + warp_m * 64 * LDS;
        const float* Bs = sB + (size_t)s * BELEM + warp_n * (TILE_N / 4) * LDS;
        #pragma unroll
        for (int kc = 0; kc < 4; kc++) {
            wmma::fragment<wmma::matrix_a, 16, 16, 8, wmma::precision::tf32, wmma::row_major> af[4];
            wmma::fragment<wmma::matrix_b, 16, 16, 8, wmma::precision::tf32, wmma::col_major> bf[NB];
            #pragma unroll
            for (int i = 0; i < 4; i++)
                wmma::load_matrix_sync(af[i], As + i * 16 * LDS + kc * 8, LDS);
            #pragma unroll
            for (int j = 0; j < NB; j++)
                wmma::load_matrix_sync(bf[j], Bs + j * 16 * LDS + kc * 8, LDS);
            #pragma unroll
            for (int i = 0; i < 4; i++)
                #pragma unroll
                for (int j = 0; j < NB; j++)
                    wmma::mma_sync(cf[i][j], af[i], bf[j], cf[i][j]);
        }
        __syncthreads();
    }

    #pragma unroll
    for (int i = 0; i < 4; i++) {
        #pragma unroll
        for (int j = 0; j < NB; j++) {
            #pragma unroll
            for (int e = 0; e < 8; e++) {
                float v = cf[i][j].x[e] * scale;
                if (ROUND) v = tf32r(v);
                cf[i][j].x[e] = v;
            }
            float* Cp = Co + (size_t)(m0 + warp_m * 64 + i * 16) * ldc
                           + n0 + warp_n * (TILE_N / 4) + j * 16;
            wmma::store_matrix_sync(Cp, cf[i][j], ldc, wmma::mem_row_major);
        }
    }
}

// ------------------------- fused softmax + P@V ------------------------------
// grid (1, SEQ/16, 32); 256 threads. Per CTA: head z, 16 q rows.
// Phase 1: softmax of S rows (in smem + written back to gmem as P).
// Phase 2: O[16,64] = P[16,2048] @ V[2048,64] via WMMA, 8-way K split.
#define SP_LD 2052   // padded row stride (floats)

__global__ void __launch_bounds__(256)
softmax_pv_kernel(float* __restrict__ S, const float* __restrict__ Vt,
                  float* __restrict__ O)
{
    extern __shared__ float sm[];
    float* sS   = sm;                    // [16][SP_LD]
    float* sRed = sm + 16 * SP_LD;       // [8][16][64]

    const int tid  = threadIdx.x;
    const int wid  = tid >> 5;
    const int lane = tid & 31;
    const int z  = blockIdx.z;
    const int b  = z >> 4, h = z & 15;
    const int q0 = blockIdx.y * 16;

    float* Sbase = S + (size_t)z * SEQ * SEQ + (size_t)q0 * SEQ;

    // ---- Phase 1: softmax on rows 2*wid and 2*wid+1 ----
    #pragma unroll
    for (int i = 0; i < 2; i++) {
        const int r = wid * 2 + i;
        float4* Srow = reinterpret_cast<float4*>(Sbase + (size_t)r * SEQ);
        float4 v[16];
        float m = -1e30f;
        #pragma unroll
        for (int j = 0; j < 16; j++) {
            v[j] = Srow[lane + j * 32];
            m = fmaxf(m, fmaxf(fmaxf(v[j].x, v[j].y), fmaxf(v[j].z, v[j].w)));
        }
        #pragma unroll
        for (int o = 16; o; o >>= 1) m = fmaxf(m, __shfl_xor_sync(0xFFFFFFFFu, m, o));
        float s = 0.f;
        #pragma unroll
        for (int j = 0; j < 16; j++) {
            v[j].x = __expf(v[j].x - m); v[j].y = __expf(v[j].y - m);
            v[j].z = __expf(v[j].z - m); v[j].w = __expf(v[j].w - m);
            s += (v[j].x + v[j].y) + (v[j].z + v[j].w);
        }
        #pragma unroll
        for (int o = 16; o; o >>= 1) s += __shfl_xor_sync(0xFFFFFFFFu, s, o);
        const float inv = 1.0f / s;
        float4* sRow = reinterpret_cast<float4*>(sS + r * SP_LD);
        #pragma unroll
        for (int j = 0; j < 16; j++) {
            float4 p;
            p.x = tf32r(v[j].x * inv); p.y = tf32r(v[j].y * inv);
            p.z = tf32r(v[j].z * inv); p.w = tf32r(v[j].w * inv);
            sRow[lane + j * 32] = p;
            Srow[lane + j * 32] = p;     // P output (in-place over S)
        }
    }
    __syncthreads();

    // ---- Phase 2: O = P @ V, warp wid handles K range [wid*256, wid*256+256) ----
    {
        const float* Vh = Vt + (size_t)z * DK * SEQ;
        wmma::fragment<wmma::accumulator, 16, 16, 8, float> acc[4];
        #pragma unroll
        for (int j = 0; j < 4; j++) wmma::fill_fragment(acc[j], 0.0f);

        const int kbase = wid * 256;
        #pragma unroll 4
        for (int kc = 0; kc < 32; kc++) {
            const int k = kbase + kc * 8;
            wmma::fragment<wmma::matrix_a, 16, 16, 8, wmma::precision::tf32, wmma::row_major> af;
            wmma::load_matrix_sync(af, sS + k, SP_LD);
            #pragma unroll
            for (int j = 0; j < 4; j++) {
                wmma::fragment<wmma::matrix_b, 16, 16, 8, wmma::precision::tf32, wmma::col_major> bf;
                wmma::load_matrix_sync(bf, Vh + (size_t)(j * 16) * SEQ + k, SEQ);
                wmma::mma_sync(acc[j], af, bf, acc[j]);
            }
        }
        #pragma unroll
        for (int j = 0; j < 4; j++)
            wmma::store_matrix_sync(sRed + wid * 1024 + j * 16, acc[j], 64, wmma::mem_row_major);
    }
    __syncthreads();

    // ---- 8-way reduction + store O ----
    for (int e = tid; e < 1024; e += 256) {
        const int r = e >> 6, c = e & 63;
        float s = 0.f;
        #pragma unroll
        for (int w = 0; w < 8; w++) s += sRed[w * 1024 + e];
        O[(size_t)(b * SEQ + q0 + r) * D_MODEL + h * DK + c] = tf32r(s);
    }
}

// ------------------------- aux kernels ---------------------------------------
__global__ void cvt_x_kernel(const float4* __restrict__ src, float4* __restrict__ dst, int n4)
{
    int i = blockIdx.x * blockDim.x + threadIdx.x;
    if (i < n4) {
        float4 v = src[i];
        v.x = tf32r(v.x); v.y = tf32r(v.y); v.z = tf32r(v.z); v.w = tf32r(v.w);
        dst[i] = v;
    }
}
__global__ void cvt_w_kernel(const float4* __restrict__ w0, const float4* __restrict__ w1,
                             const float4* __restrict__ w2, const float4* __restrict__ w3,
                             float4* __restrict__ dst)
{
    const int per = D_MODEL * D_MODEL / 4;             // 262144
    int i = blockIdx.x * blockDim.x + threadIdx.x;     // < 4*per
    const float4* src = (i < per) ? w0 : (i < 2 * per) ? w1 : (i < 3 * per) ? w2 : w3;
    float4 v = src[i & (per - 1)];
    v.x = tf32r(v.x); v.y = tf32r(v.y); v.z = tf32r(v.z); v.w = tf32r(v.w);
    dst[i] = v;
}

// V view of QKV [b, s, 2048 + h*64+d] -> Vt [(b*16+h), d, s]
__global__ void transpose_v_kernel(const float* __restrict__ QKV, float* __restrict__ Vt)
{
    __shared__ float tile[32][33];
    const int z = blockIdx.z, b = z >> 4, h = z & 15;
    const int s0 = blockIdx.x * 32, d0 = blockIdx.y * 32;
    const int tx = threadIdx.x, ty = threadIdx.y;
    #pragma unroll
    for (int i = 0; i < 4; i++) {
        int s = s0 + ty + 8 * i;
        tile[ty + 8 * i][tx] = QKV[(size_t)(b * SEQ + s) * QKVLD + 2 * D_MODEL + h * DK + d0 + tx];
    }
    __syncthreads();
    #pragma unroll
    for (int i = 0; i < 4; i++) {
        int d = d0 + ty + 8 * i;
        Vt[(size_t)z * DK * SEQ + (size_t)d * SEQ + s0 + tx] = tile[tx][ty + 8 * i];
    }
}

// ------------------------- host ----------------------------------------------
extern "C" void kernel_launch(void* const* d_in, const int* in_sizes, int n_in,
                              void* d_out, int out_size)
{
    const float* x  = (const float*)d_in[0];
    const float* Wq = (const float*)d_in[1];
    const float* Wk = (const float*)d_in[2];
    const float* Wv = (const float*)d_in[3];
    const float* Wo = (const float*)d_in[4];
    float* out = (float*)d_out;

    float *pxt, *pwt, *pQKV, *pVt, *pO;
    cudaGetSymbolAddress((void**)&pxt,  g_xt);
    cudaGetSymbolAddress((void**)&pwt,  g_wt);
    cudaGetSymbolAddress((void**)&pQKV, g_QKV);
    cudaGetSymbolAddress((void**)&pVt,  g_Vt);
    cudaGetSymbolAddress((void**)&pO,   g_O);

    const size_t projN = (size_t)MTOT * D_MODEL;
    float* S = out + projN;   // attn_weights region of d_out
    const size_t M2 = (size_t)D_MODEL * D_MODEL;

    const int smem128 = NSTAGE * (128 + 128) * LDS * 4;           // 122880 B
    const int smemSP  = (16 * SP_LD + 8 * 16 * 64) * 4;           // 164096 B
    cudaFuncSetAttribute(wmma_gemm<128, true >, cudaFuncAttributeMaxDynamicSharedMemorySize, smem128);
    cudaFuncSetAttribute(wmma_gemm<128, false>, cudaFuncAttributeMaxDynamicSharedMemorySize, smem128);
    cudaFuncSetAttribute(softmax_pv_kernel,     cudaFuncAttributeMaxDynamicSharedMemorySize, smemSP);

    // 1) tf32-round inputs (2 launches)
    cvt_x_kernel<<<(int)(projN / 4 / 256), 256>>>((const float4*)x, (float4*)pxt, (int)(projN / 4));
    cvt_w_kernel<<<(int)(4 * M2 / 4 / 256), 256>>>((const float4*)Wq, (const float4*)Wk,
                                                   (const float4*)Wv, (const float4*)Wo, (float4*)pwt);

    // 2) fused QKV projection: QKV = x @ [Wq;Wk;Wv]^T  (N=3072)
    dim3 gqkv(QKVLD / 128, MTOT / 128, 1);
    wmma_gemm<128, true><<<gqkv, 256, smem128>>>(pxt, pwt, pQKV, D_MODEL, D_MODEL, D_MODEL, QKVLD,
                                                 1.0f, 0, 0, 0, 0, 0, 0);

    // 3) transpose V per head
    transpose_v_kernel<<<dim3(SEQ / 32, DK / 32, BATCH * N_HEADS), dim3(32, 8)>>>(pQKV, pVt);

    // 4) scores S = 0.125 * Q K^T per head (Q = QKV cols 0.., K = QKV cols 1024..)
    dim3 gsc(SEQ / 128, SEQ / 128, BATCH * N_HEADS);
    wmma_gemm<128, false><<<gsc, 256, smem128>>>(pQKV, pQKV + D_MODEL, S, DK, QKVLD, QKVLD, SEQ, 0.125f,
                                                 (long long)SEQ * QKVLD, DK,
                                                 (long long)SEQ * QKVLD, DK,
                                                 (long long)16 * SEQ * SEQ, (long long)SEQ * SEQ);

    // 5) fused softmax + P@V (P written in-place over S; O accumulated)
    softmax_pv_kernel<<<dim3(1, SEQ / 16, BATCH * N_HEADS), 256, smemSP>>>(S, pVt, pO);

    // 6) out = O @ Wo^T (full fp32 store)
    dim3 gproj(D_MODEL / 128, MTOT / 128, 1);
    wmma_gemm<128, false><<<gproj, 256, smem128>>>(pO, pwt + 3 * M2, out, D_MODEL, D_MODEL, D_MODEL, D_MODEL,
                                                   1.0f, 0, 0, 0, 0, 0, 0);
}